// round 16
// baseline (speedup 1.0000x reference)
#include <cuda_runtime.h>
#include <cuda_fp16.h>
#include <math_constants.h>
#include <math.h>
#include <cstdint>

#define B_   32
#define LQ   513
#define SK   1000
#define NH   8
#define DH   128
#define DM   1024
#define DLLM 4096
#define MQ   (B_*LQ)   /* 16416 */

// ---------------- scratch (no allocation allowed) ----------------
__device__ __half h_tgt[(size_t)MQ * DM];
__device__ __half h_src[(size_t)SK * DLLM];
__device__ __half h_val[(size_t)SK * DLLM];
__device__ __half h_q  [(size_t)MQ * DM];
__device__ __half h_k  [(size_t)SK * DM];
__device__ __half h_v  [(size_t)SK * DM];
__device__ __half h_at [(size_t)MQ * DM];
__device__ __half h_wqt[(size_t)DM * DM];
__device__ __half h_wkt[(size_t)DM * DLLM];
__device__ __half h_wvt[(size_t)DM * DLLM];
__device__ __half h_wot[(size_t)DLLM * DM];

// ================= helpers =================
__device__ __forceinline__ uint32_t smem_u32(const void* p) {
    return (uint32_t)__cvta_generic_to_shared(p);
}
__device__ __forceinline__ void cp_async16(uint32_t dst, const void* src, bool valid) {
    int sz = valid ? 16 : 0;
    asm volatile("cp.async.cg.shared.global [%0], [%1], 16, %2;\n"
                 :: "r"(dst), "l"(src), "r"(sz) : "memory");
}
__device__ __forceinline__ void cp_async_commit() {
    asm volatile("cp.async.commit_group;\n" ::: "memory");
}
__device__ __forceinline__ void cp_async_wait1() {
    asm volatile("cp.async.wait_group 1;\n" ::: "memory");
}
__device__ __forceinline__ void cp_async_wait0() {
    asm volatile("cp.async.wait_group 0;\n" ::: "memory");
}
__device__ __forceinline__ void ldsm4(uint32_t& r0, uint32_t& r1, uint32_t& r2, uint32_t& r3,
                                      uint32_t addr) {
    asm volatile("ldmatrix.sync.aligned.m8n8.x4.shared.b16 {%0,%1,%2,%3}, [%4];"
                 : "=r"(r0), "=r"(r1), "=r"(r2), "=r"(r3) : "r"(addr));
}
__device__ __forceinline__ void ldsm4t(uint32_t& r0, uint32_t& r1, uint32_t& r2, uint32_t& r3,
                                       uint32_t addr) {
    asm volatile("ldmatrix.sync.aligned.m8n8.x4.trans.shared.b16 {%0,%1,%2,%3}, [%4];"
                 : "=r"(r0), "=r"(r1), "=r"(r2), "=r"(r3) : "r"(addr));
}
__device__ __forceinline__ void mma_f16(float* d, const uint32_t* a, const uint32_t* b) {
    asm volatile(
        "mma.sync.aligned.m16n8k16.row.col.f32.f16.f16.f32 "
        "{%0,%1,%2,%3}, {%4,%5,%6,%7}, {%8,%9}, {%0,%1,%2,%3};"
        : "+f"(d[0]), "+f"(d[1]), "+f"(d[2]), "+f"(d[3])
        : "r"(a[0]), "r"(a[1]), "r"(a[2]), "r"(a[3]), "r"(b[0]), "r"(b[1]));
}
__device__ __forceinline__ uint32_t h2bits(float a, float b) {
    __half2 h = __floats2half2_rn(a, b);
    return *(uint32_t*)&h;
}

// ---------------- build tgt = [cls ; target_embedding] -> half ----------------
__global__ void build_tgt_h_kernel(const float* __restrict__ tgt_emb,
                                   const float* __restrict__ cls,
                                   __half* __restrict__ out)
{
    size_t i = (size_t)blockIdx.x * blockDim.x + threadIdx.x;
    size_t total = (size_t)MQ * (DM / 4);
    if (i >= total) return;
    size_t row = i / (DM / 4);
    int    c4  = (int)(i % (DM / 4));
    int b  = (int)(row / LQ);
    int lx = (int)(row % LQ);
    float4 v;
    if (lx == 0) v = ((const float4*)cls)[c4];
    else         v = ((const float4*)tgt_emb)[ ((size_t)b * (LQ-1) + (lx-1)) * (DM/4) + c4 ];
    __half2 h0 = __floats2half2_rn(v.x, v.y);
    __half2 h1 = __floats2half2_rn(v.z, v.w);
    uint2 u = make_uint2(*(uint32_t*)&h0, *(uint32_t*)&h1);
    *(uint2*)&out[i * 4] = u;
}

// ---------------- float -> half copy ----------------
__global__ void f2h_kernel(const float* __restrict__ in, __half* __restrict__ out, size_t n4)
{
    size_t i = (size_t)blockIdx.x * blockDim.x + threadIdx.x;
    if (i >= n4) return;
    float4 v = ((const float4*)in)[i];
    __half2 h0 = __floats2half2_rn(v.x, v.y);
    __half2 h1 = __floats2half2_rn(v.z, v.w);
    uint2 u = make_uint2(*(uint32_t*)&h0, *(uint32_t*)&h1);
    *(uint2*)&out[i * 4] = u;
}

// ---------------- weight transpose -> half ----------------
__global__ void transpose_h_kernel(const float* __restrict__ in,
                                   __half* __restrict__ out, int R, int C)
{
    __shared__ float t[32][33];
    int bc = blockIdx.x * 32, br = blockIdx.y * 32;
    int tx = threadIdx.x, ty = threadIdx.y;          // 32 x 8
    #pragma unroll
    for (int i = 0; i < 32; i += 8)
        t[ty + i][tx] = in[(size_t)(br + ty + i) * C + bc + tx];
    __syncthreads();
    #pragma unroll
    for (int i = 0; i < 32; i += 8)
        out[(size_t)(bc + ty + i) * R + br + tx] = __float2half_rn(t[tx][ty + i]);
}

// ---------------- fp16 mma GEMM body (3-stage pipeline) ----------------
// CTA 128x128, BK=64, 256 thr (2x4 warps, warp tile 64x32).
#define HTILEB 16384                       /* one operand tile: 128 x 128B */
#define NSTAGE 3
#define HGEMM_SMEM (NSTAGE * 2 * HTILEB)   /* 98304 */

template <bool HOUT>
__device__ __forceinline__ void hgemm_body(
    const __half* __restrict__ A, const __half* __restrict__ Bt,
    const float* __restrict__ bias, void* __restrict__ Cv,
    int M, int N, int K, int tileX, int tileY, uint32_t s0)
{
    uint32_t SA[NSTAGE], SB[NSTAGE];
    #pragma unroll
    for (int s = 0; s < NSTAGE; s++) {
        SA[s] = s0 + s * 2 * HTILEB;
        SB[s] = s0 + s * 2 * HTILEB + HTILEB;
    }

    const int tid = threadIdx.x;
    const int lane = tid & 31, warp = tid >> 5;
    const int warpRow = warp >> 2;
    const int warpCol = warp & 3;
    const int groupID = lane >> 2, tg = lane & 3;
    const int rowBase = tileY * 128;
    const int colBase = tileX * 128;

    const int ldRow = tid >> 1;
    const int ldCb  = (tid & 1) * 4;

    const int aR = lane & 15;
    const uint32_t aK = (uint32_t)((lane >> 4) & 1) * 16;
    const int bR = (lane & 7) + ((lane >> 4) << 3);
    const uint32_t bK = (uint32_t)((lane >> 3) & 1) * 16;

    float acc[4][4][4];
    #pragma unroll
    for (int mt = 0; mt < 4; mt++)
        #pragma unroll
        for (int nt = 0; nt < 4; nt++)
            #pragma unroll
            for (int r = 0; r < 4; r++) acc[mt][nt][r] = 0.f;

    const int nkt = K >> 6;

    auto load_tile = [&](int kt, int buf) {
        const int k0 = kt << 6;
        int gr = rowBase + ldRow;
        bool av = gr < M;
        const __half* ap = A  + (size_t)(av ? gr : 0) * K + k0;
        const __half* bp = Bt + (size_t)(colBase + ldRow) * K + k0;
        const uint32_t rsw = (uint32_t)((ldRow & 7) << 4);
        const uint32_t rowoff = (uint32_t)(ldRow << 7);
        #pragma unroll
        for (int j = 0; j < 4; j++) {
            int c = ldCb + j;
            uint32_t off = (rowoff + (uint32_t)(c << 4)) ^ rsw;
            cp_async16(SA[buf] + off, ap + c * 8, av);
            cp_async16(SB[buf] + off, bp + c * 8, true);
        }
    };

    // prologue: stages 0,1 in flight
    load_tile(0, 0); cp_async_commit();
    load_tile(1, 1); cp_async_commit();

    int bufc = 0;           // kt % 3
    for (int kt = 0; kt < nkt; kt++) {
        if (kt + 1 < nkt) cp_async_wait1();   // stage kt arrived
        else              cp_async_wait0();
        __syncthreads();                       // all compute of kt-1 done chip-wide

        // prefetch stage kt+2 into buffer (kt+2)%3 == (kt-1)%3 (safe after barrier)
        if (kt + 2 < nkt) {
            int nb = bufc + 2; if (nb >= NSTAGE) nb -= NSTAGE;
            load_tile(kt + 2, nb);
            cp_async_commit();
        }

        const uint32_t sa = SA[bufc], sb = SB[bufc];
        #pragma unroll
        for (int kk = 0; kk < 4; kk++) {
            uint32_t af[4][4];
            #pragma unroll
            for (int mt = 0; mt < 4; mt++) {
                int r = warpRow * 64 + mt * 16 + aR;
                uint32_t byte = ((uint32_t)(r << 7) + (uint32_t)(kk << 5) + aK)
                                ^ (uint32_t)((r & 7) << 4);
                ldsm4(af[mt][0], af[mt][1], af[mt][2], af[mt][3], sa + byte);
            }
            uint32_t bf[2][4];
            #pragma unroll
            for (int ng = 0; ng < 2; ng++) {
                int r = warpCol * 32 + ng * 16 + bR;
                uint32_t byte = ((uint32_t)(r << 7) + (uint32_t)(kk << 5) + bK)
                                ^ (uint32_t)((r & 7) << 4);
                ldsm4(bf[ng][0], bf[ng][1], bf[ng][2], bf[ng][3], sb + byte);
            }
            #pragma unroll
            for (int mt = 0; mt < 4; mt++) {
                mma_f16(acc[mt][0], af[mt], &bf[0][0]);
                mma_f16(acc[mt][1], af[mt], &bf[0][2]);
                mma_f16(acc[mt][2], af[mt], &bf[1][0]);
                mma_f16(acc[mt][3], af[mt], &bf[1][2]);
            }
        }
        if (++bufc == NSTAGE) bufc = 0;
    }

    // ---- epilogue: +bias ----
    #pragma unroll
    for (int nt = 0; nt < 4; nt++) {
        int gn = colBase + warpCol * 32 + nt * 8 + 2 * tg;
        float bx = bias[gn], by = bias[gn + 1];
        #pragma unroll
        for (int mt = 0; mt < 4; mt++) {
            int gm0 = rowBase + warpRow * 64 + mt * 16 + groupID;
            if (gm0 < M) {
                if (HOUT) {
                    __half2 hv = __floats2half2_rn(acc[mt][nt][0] + bx, acc[mt][nt][1] + by);
                    *(__half2*)&((__half*)Cv)[(size_t)gm0 * N + gn] = hv;
                } else {
                    float2 v = make_float2(acc[mt][nt][0] + bx, acc[mt][nt][1] + by);
                    *(float2*)&((float*)Cv)[(size_t)gm0 * N + gn] = v;
                }
            }
            if (gm0 + 8 < M) {
                if (HOUT) {
                    __half2 hv = __floats2half2_rn(acc[mt][nt][2] + bx, acc[mt][nt][3] + by);
                    *(__half2*)&((__half*)Cv)[(size_t)(gm0 + 8) * N + gn] = hv;
                } else {
                    float2 v = make_float2(acc[mt][nt][2] + bx, acc[mt][nt][3] + by);
                    *(float2*)&((float*)Cv)[(size_t)(gm0 + 8) * N + gn] = v;
                }
            }
        }
    }
}

// ---------------- fused Q/K/V projection (one launch, 1160 tiles) ------------
#define QKV_QTILES (8 * 129)      /* 1032 */
#define QKV_KVT    (8 * 8)        /* 64 per op */
#define QKV_BLOCKS (QKV_QTILES + 2 * QKV_KVT)

__global__ __launch_bounds__(256, 2) void qkv_gemm_kernel(
    const float* __restrict__ bq, const float* __restrict__ bk,
    const float* __restrict__ bv)
{
    extern __shared__ char smemc[];
    const uint32_t s0 = smem_u32(smemc);
    int bid = blockIdx.x;
    if (bid < QKV_QTILES) {
        int ty = bid >> 3, tx = bid & 7;
        hgemm_body<true>(h_tgt, h_wqt, bq, h_q, MQ, DM, DM, tx, ty, s0);
    } else if (bid < QKV_QTILES + QKV_KVT) {
        int r = bid - QKV_QTILES;
        int ty = r >> 3, tx = r & 7;
        hgemm_body<true>(h_src, h_wkt, bk, h_k, SK, DM, DLLM, tx, ty, s0);
    } else {
        int r = bid - QKV_QTILES - QKV_KVT;
        int ty = r >> 3, tx = r & 7;
        hgemm_body<true>(h_val, h_wvt, bv, h_v, SK, DM, DLLM, tx, ty, s0);
    }
}

// ---------------- output projection ----------------
__global__ __launch_bounds__(256, 2) void oproj_kernel(
    const float* __restrict__ bo, float* __restrict__ out)
{
    extern __shared__ char smemc[];
    const uint32_t s0 = smem_u32(smemc);
    hgemm_body<false>(h_at, h_wot, bo, out, MQ, DLLM, DM,
                      blockIdx.x, blockIdx.y, s0);
}

// ---------------- fp16 tensor-core flash attention ----------------
#define ATILE 16384                     /* 64 rows x 256B */
#define ATTN_SMEM (5 * ATILE)           /* Q + 2x(K,V) = 80KB */

__global__ __launch_bounds__(128) void fattn_kernel()
{
    extern __shared__ char smemc[];
    const uint32_t s0 = smem_u32(smemc);
    const uint32_t SQ = s0;
    const uint32_t SKb[2] = { s0 + ATILE,     s0 + 3 * ATILE };
    const uint32_t SVb[2] = { s0 + 2 * ATILE, s0 + 4 * ATILE };

    const int tid = threadIdx.x, lane = tid & 31, warp = tid >> 5;
    const int g = lane >> 2, tg = lane & 3;
    const int b = blockIdx.z, h = blockIdx.y, qt = blockIdx.x;
    const int q0 = qt * 64;
    const float SCALE = 0.08838834764831845f;

    {
        int r = tid >> 1;
        int gq = q0 + r;
        bool ok = gq < LQ;
        const __half* src = h_q + ((size_t)b * LQ + (ok ? gq : 0)) * DM + h * DH;
        uint32_t rsw = (uint32_t)((r & 7) << 4);
        #pragma unroll
        for (int j = 0; j < 8; j++) {
            int c = (tid & 1) * 8 + j;
            uint32_t off = ((uint32_t)(r * 256 + c * 16)) ^ rsw;
            cp_async16(SQ + off, src + c * 8, ok);
        }
    }
    cp_async_commit();

    auto loadKV = [&](int it, int bufi) {
        int r = tid >> 1;
        int gs = it * 64 + r;
        bool ok = gs < SK;
        const __half* ks = h_k + (size_t)(ok ? gs : 0) * DM + h * DH;
        const __half* vs = h_v + (size_t)(ok ? gs : 0) * DM + h * DH;
        uint32_t rsw = (uint32_t)((r & 7) << 4);
        #pragma unroll
        for (int j = 0; j < 8; j++) {
            int c = (tid & 1) * 8 + j;
            uint32_t off = ((uint32_t)(r * 256 + c * 16)) ^ rsw;
            cp_async16(SKb[bufi] + off, ks + c * 8, ok);
            cp_async16(SVb[bufi] + off, vs + c * 8, ok);
        }
    };
    loadKV(0, 0);
    cp_async_commit();
    cp_async_wait1();
    __syncthreads();

    uint32_t qf[8][4];
    {
        int aR = lane & 15;
        uint32_t aK = (uint32_t)((lane >> 4) & 1) * 16;
        int r = warp * 16 + aR;
        uint32_t rsw = (uint32_t)((r & 7) << 4);
        #pragma unroll
        for (int kk = 0; kk < 8; kk++) {
            uint32_t byte = ((uint32_t)(r * 256 + kk * 32) + aK) ^ rsw;
            ldsm4(qf[kk][0], qf[kk][1], qf[kk][2], qf[kk][3], SQ + byte);
        }
    }

    float acc_o[16][4];
    #pragma unroll
    for (int nt = 0; nt < 16; nt++)
        #pragma unroll
        for (int r = 0; r < 4; r++) acc_o[nt][r] = 0.f;
    float m0 = -CUDART_INF_F, m1 = -CUDART_INF_F, l0 = 0.f, l1 = 0.f;

    const int NST = (SK + 63) / 64;
    int buf = 0;
    for (int it = 0; it < NST; it++) {
        if (it + 1 < NST) { loadKV(it + 1, buf ^ 1); cp_async_commit(); cp_async_wait1(); }
        else              { cp_async_wait0(); }
        __syncthreads();

        float s[8][4];
        #pragma unroll
        for (int nt = 0; nt < 8; nt++)
            #pragma unroll
            for (int r = 0; r < 4; r++) s[nt][r] = 0.f;
        {
            int bR = (lane & 7) + ((lane >> 4) << 3);
            uint32_t bK = (uint32_t)((lane >> 3) & 1) * 16;
            #pragma unroll
            for (int kk = 0; kk < 8; kk++) {
                uint32_t bfr[4][4];
                #pragma unroll
                for (int ng = 0; ng < 4; ng++) {
                    int r = ng * 16 + bR;
                    uint32_t byte = ((uint32_t)(r * 256 + kk * 32) + bK)
                                    ^ (uint32_t)((r & 7) << 4);
                    ldsm4(bfr[ng][0], bfr[ng][1], bfr[ng][2], bfr[ng][3], SKb[buf] + byte);
                }
                #pragma unroll
                for (int ng = 0; ng < 4; ng++) {
                    mma_f16(s[2 * ng],     qf[kk], &bfr[ng][0]);
                    mma_f16(s[2 * ng + 1], qf[kk], &bfr[ng][2]);
                }
            }
        }

        int sbase = it * 64;
        #pragma unroll
        for (int nt = 0; nt < 8; nt++) {
            int c0 = sbase + nt * 8 + 2 * tg;
            bool v0 = c0 < SK, v1 = (c0 + 1) < SK;
            s[nt][0] = v0 ? s[nt][0] * SCALE : -CUDART_INF_F;
            s[nt][1] = v1 ? s[nt][1] * SCALE : -CUDART_INF_F;
            s[nt][2] = v0 ? s[nt][2] * SCALE : -CUDART_INF_F;
            s[nt][3] = v1 ? s[nt][3] * SCALE : -CUDART_INF_F;
        }

        float rm0 = -CUDART_INF_F, rm1 = -CUDART_INF_F;
        #pragma unroll
        for (int nt = 0; nt < 8; nt++) {
            rm0 = fmaxf(rm0, fmaxf(s[nt][0], s[nt][1]));
            rm1 = fmaxf(rm1, fmaxf(s[nt][2], s[nt][3]));
        }
        rm0 = fmaxf(rm0, __shfl_xor_sync(0xffffffff, rm0, 1));
        rm0 = fmaxf(rm0, __shfl_xor_sync(0xffffffff, rm0, 2));
        rm1 = fmaxf(rm1, __shfl_xor_sync(0xffffffff, rm1, 1));
        rm1 = fmaxf(rm1, __shfl_xor_sync(0xffffffff, rm1, 2));
        float mn0 = fmaxf(m0, rm0), mn1 = fmaxf(m1, rm1);
        float a0 = __expf(m0 - mn0), a1 = __expf(m1 - mn1);

        float ps0 = 0.f, ps1 = 0.f;
        #pragma unroll
        for (int nt = 0; nt < 8; nt++) {
            s[nt][0] = __expf(s[nt][0] - mn0);
            s[nt][1] = __expf(s[nt][1] - mn0);
            s[nt][2] = __expf(s[nt][2] - mn1);
            s[nt][3] = __expf(s[nt][3] - mn1);
            ps0 += s[nt][0] + s[nt][1];
            ps1 += s[nt][2] + s[nt][3];
        }
        ps0 += __shfl_xor_sync(0xffffffff, ps0, 1);
        ps0 += __shfl_xor_sync(0xffffffff, ps0, 2);
        ps1 += __shfl_xor_sync(0xffffffff, ps1, 1);
        ps1 += __shfl_xor_sync(0xffffffff, ps1, 2);
        l0 = l0 * a0 + ps0;
        l1 = l1 * a1 + ps1;
        m0 = mn0; m1 = mn1;

        #pragma unroll
        for (int nt = 0; nt < 16; nt++) {
            acc_o[nt][0] *= a0; acc_o[nt][1] *= a0;
            acc_o[nt][2] *= a1; acc_o[nt][3] *= a1;
        }

        uint32_t pf[4][4];
        #pragma unroll
        for (int kt = 0; kt < 4; kt++) {
            pf[kt][0] = h2bits(s[2 * kt][0],     s[2 * kt][1]);
            pf[kt][1] = h2bits(s[2 * kt][2],     s[2 * kt][3]);
            pf[kt][2] = h2bits(s[2 * kt + 1][0], s[2 * kt + 1][1]);
            pf[kt][3] = h2bits(s[2 * kt + 1][2], s[2 * kt + 1][3]);
        }

        {
            int vR = lane & 15;
            uint32_t vC = (uint32_t)((lane >> 4) & 1) * 16;
            #pragma unroll
            for (int kt = 0; kt < 4; kt++) {
                int r = kt * 16 + vR;
                uint32_t rsw = (uint32_t)((r & 7) << 4);
                uint32_t rowb = (uint32_t)(r * 256);
                #pragma unroll
                for (int nn = 0; nn < 8; nn++) {
                    uint32_t byte = (rowb + (uint32_t)(nn * 32) + vC) ^ rsw;
                    uint32_t v0, v1, v2, v3;
                    ldsm4t(v0, v1, v2, v3, SVb[buf] + byte);
                    uint32_t bb0[2] = { v0, v1 }, bb1[2] = { v2, v3 };
                    mma_f16(acc_o[2 * nn],     pf[kt], bb0);
                    mma_f16(acc_o[2 * nn + 1], pf[kt], bb1);
                }
            }
        }
        __syncthreads();
        buf ^= 1;
    }

    float inv0 = 1.f / l0, inv1 = 1.f / l1;
    int gq0 = q0 + warp * 16 + g, gq1 = gq0 + 8;
    #pragma unroll
    for (int nt = 0; nt < 16; nt++) {
        int col = h * DH + nt * 8 + 2 * tg;
        if (gq0 < LQ) {
            __half2 hv = __floats2half2_rn(acc_o[nt][0] * inv0, acc_o[nt][1] * inv0);
            *(__half2*)&h_at[((size_t)b * LQ + gq0) * DM + col] = hv;
        }
        if (gq1 < LQ) {
            __half2 hv = __floats2half2_rn(acc_o[nt][2] * inv1, acc_o[nt][3] * inv1);
            *(__half2*)&h_at[((size_t)b * LQ + gq1) * DM + col] = hv;
        }
    }
}

// ---------------- launcher ----------------
extern "C" void kernel_launch(void* const* d_in, const int* in_sizes, int n_in,
                              void* d_out, int out_size)
{
    const float* tgt = (const float*)d_in[0];
    const float* src = (const float*)d_in[1];
    const float* val = (const float*)d_in[2];
    const float* Wq  = (const float*)d_in[3];
    const float* bq  = (const float*)d_in[4];
    const float* Wk  = (const float*)d_in[5];
    const float* bk  = (const float*)d_in[6];
    const float* Wv  = (const float*)d_in[7];
    const float* bv  = (const float*)d_in[8];
    const float* Wo  = (const float*)d_in[9];
    const float* bo  = (const float*)d_in[10];
    const float* cls = (const float*)d_in[11];

    __half *p_tgt, *p_src, *p_val, *p_wqt, *p_wkt, *p_wvt, *p_wot;
    cudaGetSymbolAddress((void**)&p_tgt, h_tgt);
    cudaGetSymbolAddress((void**)&p_src, h_src);
    cudaGetSymbolAddress((void**)&p_val, h_val);
    cudaGetSymbolAddress((void**)&p_wqt, h_wqt);
    cudaGetSymbolAddress((void**)&p_wkt, h_wkt);
    cudaGetSymbolAddress((void**)&p_wvt, h_wvt);
    cudaGetSymbolAddress((void**)&p_wot, h_wot);

    cudaFuncSetAttribute(qkv_gemm_kernel, cudaFuncAttributeMaxDynamicSharedMemorySize, HGEMM_SMEM);
    cudaFuncSetAttribute(oproj_kernel,    cudaFuncAttributeMaxDynamicSharedMemorySize, HGEMM_SMEM);
    cudaFuncSetAttribute(fattn_kernel,    cudaFuncAttributeMaxDynamicSharedMemorySize, ATTN_SMEM);

    dim3 tb(32, 8);
    transpose_h_kernel<<<dim3(DM / 32,   DM / 32),   tb>>>(Wq, p_wqt, DM,   DM);
    transpose_h_kernel<<<dim3(DM / 32,   DLLM / 32), tb>>>(Wk, p_wkt, DLLM, DM);
    transpose_h_kernel<<<dim3(DM / 32,   DLLM / 32), tb>>>(Wv, p_wvt, DLLM, DM);
    transpose_h_kernel<<<dim3(DLLM / 32, DM / 32),   tb>>>(Wo, p_wot, DM,   DLLM);

    {
        size_t total = (size_t)MQ * (DM / 4);
        build_tgt_h_kernel<<<(int)((total + 255) / 256), 256>>>(tgt, cls, p_tgt);
        size_t n4 = (size_t)SK * DLLM / 4;
        f2h_kernel<<<(int)((n4 + 255) / 256), 256>>>(src, p_src, n4);
        f2h_kernel<<<(int)((n4 + 255) / 256), 256>>>(val, p_val, n4);
    }

    // fused Q/K/V projections (one launch, 1160 tiles)
    qkv_gemm_kernel<<<QKV_BLOCKS, 256, HGEMM_SMEM>>>(bq, bk, bv);
    // attention (half in, half out)
    fattn_kernel<<<dim3((LQ + 63) / 64, NH, B_), 128, ATTN_SMEM>>>();
    // out = attn @ Wo + bo         [16416,4096]  (float out)
    oproj_kernel<<<dim3(DLLM / 128, (MQ + 127) / 128), 256, HGEMM_SMEM>>>(bo, (float*)d_out);
}

// round 17
// speedup vs baseline: 1.5846x; 1.5846x over previous
#include <cuda_runtime.h>
#include <cuda_fp16.h>
#include <math_constants.h>
#include <math.h>
#include <cstdint>

#define B_   32
#define LQ   513
#define SK   1000
#define NH   8
#define DH   128
#define DM   1024
#define DLLM 4096
#define MQ   (B_*LQ)   /* 16416 */

// ---------------- scratch (no allocation allowed) ----------------
__device__ __half h_tgt[(size_t)MQ * DM];
__device__ __half h_src[(size_t)SK * DLLM];
__device__ __half h_val[(size_t)SK * DLLM];
__device__ __half h_q  [(size_t)MQ * DM];
__device__ __half h_k  [(size_t)SK * DM];
__device__ __half h_v  [(size_t)SK * DM];
__device__ __half h_at [(size_t)MQ * DM];
__device__ __half h_wqt[(size_t)DM * DM];
__device__ __half h_wkt[(size_t)DM * DLLM];
__device__ __half h_wvt[(size_t)DM * DLLM];
__device__ __half h_wot[(size_t)DLLM * DM];

// ================= helpers =================
__device__ __forceinline__ uint32_t smem_u32(const void* p) {
    return (uint32_t)__cvta_generic_to_shared(p);
}
__device__ __forceinline__ void cp_async16(uint32_t dst, const void* src, bool valid) {
    int sz = valid ? 16 : 0;
    asm volatile("cp.async.cg.shared.global [%0], [%1], 16, %2;\n"
                 :: "r"(dst), "l"(src), "r"(sz) : "memory");
}
__device__ __forceinline__ void cp_async_commit() {
    asm volatile("cp.async.commit_group;\n" ::: "memory");
}
__device__ __forceinline__ void cp_async_wait1() {
    asm volatile("cp.async.wait_group 1;\n" ::: "memory");
}
__device__ __forceinline__ void cp_async_wait0() {
    asm volatile("cp.async.wait_group 0;\n" ::: "memory");
}
__device__ __forceinline__ void ldsm4(uint32_t& r0, uint32_t& r1, uint32_t& r2, uint32_t& r3,
                                      uint32_t addr) {
    asm volatile("ldmatrix.sync.aligned.m8n8.x4.shared.b16 {%0,%1,%2,%3}, [%4];"
                 : "=r"(r0), "=r"(r1), "=r"(r2), "=r"(r3) : "r"(addr));
}
__device__ __forceinline__ void ldsm4t(uint32_t& r0, uint32_t& r1, uint32_t& r2, uint32_t& r3,
                                       uint32_t addr) {
    asm volatile("ldmatrix.sync.aligned.m8n8.x4.trans.shared.b16 {%0,%1,%2,%3}, [%4];"
                 : "=r"(r0), "=r"(r1), "=r"(r2), "=r"(r3) : "r"(addr));
}
__device__ __forceinline__ void mma_f16(float* d, const uint32_t* a, const uint32_t* b) {
    asm volatile(
        "mma.sync.aligned.m16n8k16.row.col.f32.f16.f16.f32 "
        "{%0,%1,%2,%3}, {%4,%5,%6,%7}, {%8,%9}, {%0,%1,%2,%3};"
        : "+f"(d[0]), "+f"(d[1]), "+f"(d[2]), "+f"(d[3])
        : "r"(a[0]), "r"(a[1]), "r"(a[2]), "r"(a[3]), "r"(b[0]), "r"(b[1]));
}
__device__ __forceinline__ uint32_t h2bits(float a, float b) {
    __half2 h = __floats2half2_rn(a, b);
    return *(uint32_t*)&h;
}

// ---------------- build tgt = [cls ; target_embedding] -> half ----------------
__global__ void build_tgt_h_kernel(const float* __restrict__ tgt_emb,
                                   const float* __restrict__ cls,
                                   __half* __restrict__ out)
{
    size_t i = (size_t)blockIdx.x * blockDim.x + threadIdx.x;
    size_t total = (size_t)MQ * (DM / 4);
    if (i >= total) return;
    size_t row = i / (DM / 4);
    int    c4  = (int)(i % (DM / 4));
    int b  = (int)(row / LQ);
    int lx = (int)(row % LQ);
    float4 v;
    if (lx == 0) v = ((const float4*)cls)[c4];
    else         v = ((const float4*)tgt_emb)[ ((size_t)b * (LQ-1) + (lx-1)) * (DM/4) + c4 ];
    __half2 h0 = __floats2half2_rn(v.x, v.y);
    __half2 h1 = __floats2half2_rn(v.z, v.w);
    uint2 u = make_uint2(*(uint32_t*)&h0, *(uint32_t*)&h1);
    *(uint2*)&out[i * 4] = u;
}

// ---------------- float -> half copy ----------------
__global__ void f2h_kernel(const float* __restrict__ in, __half* __restrict__ out, size_t n4)
{
    size_t i = (size_t)blockIdx.x * blockDim.x + threadIdx.x;
    if (i >= n4) return;
    float4 v = ((const float4*)in)[i];
    __half2 h0 = __floats2half2_rn(v.x, v.y);
    __half2 h1 = __floats2half2_rn(v.z, v.w);
    uint2 u = make_uint2(*(uint32_t*)&h0, *(uint32_t*)&h1);
    *(uint2*)&out[i * 4] = u;
}

// ---------------- weight transpose -> half ----------------
__global__ void transpose_h_kernel(const float* __restrict__ in,
                                   __half* __restrict__ out, int R, int C)
{
    __shared__ float t[32][33];
    int bc = blockIdx.x * 32, br = blockIdx.y * 32;
    int tx = threadIdx.x, ty = threadIdx.y;          // 32 x 8
    #pragma unroll
    for (int i = 0; i < 32; i += 8)
        t[ty + i][tx] = in[(size_t)(br + ty + i) * C + bc + tx];
    __syncthreads();
    #pragma unroll
    for (int i = 0; i < 32; i += 8)
        out[(size_t)(bc + ty + i) * R + br + tx] = __float2half_rn(t[tx][ty + i]);
}

// ---------------- fp16 mma GEMM body (R13 double-buffer, prefetch-first) ----
// CTA 128x128, BK=64, 256 thr (2x4 warps, warp tile 64x32).
#define HTILEB 16384
#define HGEMM_SMEM (4 * HTILEB)            /* 65536 */

template <bool HOUT>
__device__ __forceinline__ void hgemm_body(
    const __half* __restrict__ A, const __half* __restrict__ Bt,
    const float* __restrict__ bias, void* __restrict__ Cv,
    int M, int N, int K, int tileX, int tileY, uint32_t s0)
{
    const uint32_t SA[2] = { s0,          s0 + 2 * HTILEB };
    const uint32_t SB[2] = { s0 + HTILEB, s0 + 3 * HTILEB };

    const int tid = threadIdx.x;
    const int lane = tid & 31, warp = tid >> 5;
    const int warpRow = warp >> 2;
    const int warpCol = warp & 3;
    const int groupID = lane >> 2, tg = lane & 3;
    const int rowBase = tileY * 128;
    const int colBase = tileX * 128;

    const int ldRow = tid >> 1;
    const int ldCb  = (tid & 1) * 4;

    const int aR = lane & 15;
    const uint32_t aK = (uint32_t)((lane >> 4) & 1) * 16;
    const int bR = (lane & 7) + ((lane >> 4) << 3);
    const uint32_t bK = (uint32_t)((lane >> 3) & 1) * 16;

    float acc[4][4][4];
    #pragma unroll
    for (int mt = 0; mt < 4; mt++)
        #pragma unroll
        for (int nt = 0; nt < 4; nt++)
            #pragma unroll
            for (int r = 0; r < 4; r++) acc[mt][nt][r] = 0.f;

    const int nkt = K >> 6;

    auto load_tile = [&](int kt, int buf) {
        const int k0 = kt << 6;
        int gr = rowBase + ldRow;
        bool av = gr < M;
        const __half* ap = A  + (size_t)(av ? gr : 0) * K + k0;
        const __half* bp = Bt + (size_t)(colBase + ldRow) * K + k0;
        const uint32_t rsw = (uint32_t)((ldRow & 7) << 4);
        const uint32_t rowoff = (uint32_t)(ldRow << 7);
        #pragma unroll
        for (int j = 0; j < 4; j++) {
            int c = ldCb + j;
            uint32_t off = (rowoff + (uint32_t)(c << 4)) ^ rsw;
            cp_async16(SA[buf] + off, ap + c * 8, av);
            cp_async16(SB[buf] + off, bp + c * 8, true);
        }
    };

    load_tile(0, 0);
    cp_async_commit();

    int buf = 0;
    for (int kt = 0; kt < nkt; kt++) {
        if (kt + 1 < nkt) {
            load_tile(kt + 1, buf ^ 1);
            cp_async_commit();
            cp_async_wait1();
        } else {
            cp_async_wait0();
        }
        __syncthreads();

        const uint32_t sa = SA[buf], sb = SB[buf];
        #pragma unroll
        for (int kk = 0; kk < 4; kk++) {
            uint32_t af[4][4];
            #pragma unroll
            for (int mt = 0; mt < 4; mt++) {
                int r = warpRow * 64 + mt * 16 + aR;
                uint32_t byte = ((uint32_t)(r << 7) + (uint32_t)(kk << 5) + aK)
                                ^ (uint32_t)((r & 7) << 4);
                ldsm4(af[mt][0], af[mt][1], af[mt][2], af[mt][3], sa + byte);
            }
            uint32_t bf[2][4];
            #pragma unroll
            for (int ng = 0; ng < 2; ng++) {
                int r = warpCol * 32 + ng * 16 + bR;
                uint32_t byte = ((uint32_t)(r << 7) + (uint32_t)(kk << 5) + bK)
                                ^ (uint32_t)((r & 7) << 4);
                ldsm4(bf[ng][0], bf[ng][1], bf[ng][2], bf[ng][3], sb + byte);
            }
            #pragma unroll
            for (int mt = 0; mt < 4; mt++) {
                mma_f16(acc[mt][0], af[mt], &bf[0][0]);
                mma_f16(acc[mt][1], af[mt], &bf[0][2]);
                mma_f16(acc[mt][2], af[mt], &bf[1][0]);
                mma_f16(acc[mt][3], af[mt], &bf[1][2]);
            }
        }
        __syncthreads();
        buf ^= 1;
    }

    // ---- epilogue: +bias ----
    #pragma unroll
    for (int nt = 0; nt < 4; nt++) {
        int gn = colBase + warpCol * 32 + nt * 8 + 2 * tg;
        float bx = bias[gn], by = bias[gn + 1];
        #pragma unroll
        for (int mt = 0; mt < 4; mt++) {
            int gm0 = rowBase + warpRow * 64 + mt * 16 + groupID;
            if (gm0 < M) {
                if (HOUT) {
                    __half2 hv = __floats2half2_rn(acc[mt][nt][0] + bx, acc[mt][nt][1] + by);
                    *(__half2*)&((__half*)Cv)[(size_t)gm0 * N + gn] = hv;
                } else {
                    float2 v = make_float2(acc[mt][nt][0] + bx, acc[mt][nt][1] + by);
                    *(float2*)&((float*)Cv)[(size_t)gm0 * N + gn] = v;
                }
            }
            if (gm0 + 8 < M) {
                if (HOUT) {
                    __half2 hv = __floats2half2_rn(acc[mt][nt][2] + bx, acc[mt][nt][3] + by);
                    *(__half2*)&((__half*)Cv)[(size_t)(gm0 + 8) * N + gn] = hv;
                } else {
                    float2 v = make_float2(acc[mt][nt][2] + bx, acc[mt][nt][3] + by);
                    *(float2*)&((float*)Cv)[(size_t)(gm0 + 8) * N + gn] = v;
                }
            }
        }
    }
}

// ---------------- fused Q/K/V projection — LONG TILES FIRST -----------------
// blocks 0..63   : K tiles (K=4096, 64 k-iters)   — longest, scheduled first
// blocks 64..127 : V tiles (K=4096, 64 k-iters)
// blocks 128..   : Q tiles (K=1024, 16 k-iters)   — pack in behind
#define QKV_KVT    64             /* 8x8 per op */
#define QKV_QTILES (8 * 129)      /* 1032 */
#define QKV_BLOCKS (2 * QKV_KVT + QKV_QTILES)

__global__ __launch_bounds__(256, 2) void qkv_gemm_kernel(
    const float* __restrict__ bq, const float* __restrict__ bk,
    const float* __restrict__ bv)
{
    extern __shared__ char smemc[];
    const uint32_t s0 = smem_u32(smemc);
    int bid = blockIdx.x;
    if (bid < QKV_KVT) {
        int ty = bid >> 3, tx = bid & 7;
        hgemm_body<true>(h_src, h_wkt, bk, h_k, SK, DM, DLLM, tx, ty, s0);
    } else if (bid < 2 * QKV_KVT) {
        int r = bid - QKV_KVT;
        int ty = r >> 3, tx = r & 7;
        hgemm_body<true>(h_val, h_wvt, bv, h_v, SK, DM, DLLM, tx, ty, s0);
    } else {
        int r = bid - 2 * QKV_KVT;
        int ty = r >> 3, tx = r & 7;
        hgemm_body<true>(h_tgt, h_wqt, bq, h_q, MQ, DM, DM, tx, ty, s0);
    }
}

// ---------------- output projection ----------------
__global__ __launch_bounds__(256, 2) void oproj_kernel(
    const float* __restrict__ bo, float* __restrict__ out)
{
    extern __shared__ char smemc[];
    const uint32_t s0 = smem_u32(smemc);
    hgemm_body<false>(h_at, h_wot, bo, out, MQ, DLLM, DM,
                      blockIdx.x, blockIdx.y, s0);
}

// ---------------- fp16 tensor-core flash attention ----------------
#define ATILE 16384                     /* 64 rows x 256B */
#define ATTN_SMEM (5 * ATILE)           /* Q + 2x(K,V) = 80KB */

__global__ __launch_bounds__(128) void fattn_kernel()
{
    extern __shared__ char smemc[];
    const uint32_t s0 = smem_u32(smemc);
    const uint32_t SQ = s0;
    const uint32_t SKb[2] = { s0 + ATILE,     s0 + 3 * ATILE };
    const uint32_t SVb[2] = { s0 + 2 * ATILE, s0 + 4 * ATILE };

    const int tid = threadIdx.x, lane = tid & 31, warp = tid >> 5;
    const int g = lane >> 2, tg = lane & 3;
    const int b = blockIdx.z, h = blockIdx.y, qt = blockIdx.x;
    const int q0 = qt * 64;
    const float SCALE = 0.08838834764831845f;

    {
        int r = tid >> 1;
        int gq = q0 + r;
        bool ok = gq < LQ;
        const __half* src = h_q + ((size_t)b * LQ + (ok ? gq : 0)) * DM + h * DH;
        uint32_t rsw = (uint32_t)((r & 7) << 4);
        #pragma unroll
        for (int j = 0; j < 8; j++) {
            int c = (tid & 1) * 8 + j;
            uint32_t off = ((uint32_t)(r * 256 + c * 16)) ^ rsw;
            cp_async16(SQ + off, src + c * 8, ok);
        }
    }
    cp_async_commit();

    auto loadKV = [&](int it, int bufi) {
        int r = tid >> 1;
        int gs = it * 64 + r;
        bool ok = gs < SK;
        const __half* ks = h_k + (size_t)(ok ? gs : 0) * DM + h * DH;
        const __half* vs = h_v + (size_t)(ok ? gs : 0) * DM + h * DH;
        uint32_t rsw = (uint32_t)((r & 7) << 4);
        #pragma unroll
        for (int j = 0; j < 8; j++) {
            int c = (tid & 1) * 8 + j;
            uint32_t off = ((uint32_t)(r * 256 + c * 16)) ^ rsw;
            cp_async16(SKb[bufi] + off, ks + c * 8, ok);
            cp_async16(SVb[bufi] + off, vs + c * 8, ok);
        }
    };
    loadKV(0, 0);
    cp_async_commit();
    cp_async_wait1();
    __syncthreads();

    uint32_t qf[8][4];
    {
        int aR = lane & 15;
        uint32_t aK = (uint32_t)((lane >> 4) & 1) * 16;
        int r = warp * 16 + aR;
        uint32_t rsw = (uint32_t)((r & 7) << 4);
        #pragma unroll
        for (int kk = 0; kk < 8; kk++) {
            uint32_t byte = ((uint32_t)(r * 256 + kk * 32) + aK) ^ rsw;
            ldsm4(qf[kk][0], qf[kk][1], qf[kk][2], qf[kk][3], SQ + byte);
        }
    }

    float acc_o[16][4];
    #pragma unroll
    for (int nt = 0; nt < 16; nt++)
        #pragma unroll
        for (int r = 0; r < 4; r++) acc_o[nt][r] = 0.f;
    float m0 = -CUDART_INF_F, m1 = -CUDART_INF_F, l0 = 0.f, l1 = 0.f;

    const int NST = (SK + 63) / 64;
    int buf = 0;
    for (int it = 0; it < NST; it++) {
        if (it + 1 < NST) { loadKV(it + 1, buf ^ 1); cp_async_commit(); cp_async_wait1(); }
        else              { cp_async_wait0(); }
        __syncthreads();

        float s[8][4];
        #pragma unroll
        for (int nt = 0; nt < 8; nt++)
            #pragma unroll
            for (int r = 0; r < 4; r++) s[nt][r] = 0.f;
        {
            int bR = (lane & 7) + ((lane >> 4) << 3);
            uint32_t bK = (uint32_t)((lane >> 3) & 1) * 16;
            #pragma unroll
            for (int kk = 0; kk < 8; kk++) {
                uint32_t bfr[4][4];
                #pragma unroll
                for (int ng = 0; ng < 4; ng++) {
                    int r = ng * 16 + bR;
                    uint32_t byte = ((uint32_t)(r * 256 + kk * 32) + bK)
                                    ^ (uint32_t)((r & 7) << 4);
                    ldsm4(bfr[ng][0], bfr[ng][1], bfr[ng][2], bfr[ng][3], SKb[buf] + byte);
                }
                #pragma unroll
                for (int ng = 0; ng < 4; ng++) {
                    mma_f16(s[2 * ng],     qf[kk], &bfr[ng][0]);
                    mma_f16(s[2 * ng + 1], qf[kk], &bfr[ng][2]);
                }
            }
        }

        int sbase = it * 64;
        #pragma unroll
        for (int nt = 0; nt < 8; nt++) {
            int c0 = sbase + nt * 8 + 2 * tg;
            bool v0 = c0 < SK, v1 = (c0 + 1) < SK;
            s[nt][0] = v0 ? s[nt][0] * SCALE : -CUDART_INF_F;
            s[nt][1] = v1 ? s[nt][1] * SCALE : -CUDART_INF_F;
            s[nt][2] = v0 ? s[nt][2] * SCALE : -CUDART_INF_F;
            s[nt][3] = v1 ? s[nt][3] * SCALE : -CUDART_INF_F;
        }

        float rm0 = -CUDART_INF_F, rm1 = -CUDART_INF_F;
        #pragma unroll
        for (int nt = 0; nt < 8; nt++) {
            rm0 = fmaxf(rm0, fmaxf(s[nt][0], s[nt][1]));
            rm1 = fmaxf(rm1, fmaxf(s[nt][2], s[nt][3]));
        }
        rm0 = fmaxf(rm0, __shfl_xor_sync(0xffffffff, rm0, 1));
        rm0 = fmaxf(rm0, __shfl_xor_sync(0xffffffff, rm0, 2));
        rm1 = fmaxf(rm1, __shfl_xor_sync(0xffffffff, rm1, 1));
        rm1 = fmaxf(rm1, __shfl_xor_sync(0xffffffff, rm1, 2));
        float mn0 = fmaxf(m0, rm0), mn1 = fmaxf(m1, rm1);
        float a0 = __expf(m0 - mn0), a1 = __expf(m1 - mn1);

        float ps0 = 0.f, ps1 = 0.f;
        #pragma unroll
        for (int nt = 0; nt < 8; nt++) {
            s[nt][0] = __expf(s[nt][0] - mn0);
            s[nt][1] = __expf(s[nt][1] - mn0);
            s[nt][2] = __expf(s[nt][2] - mn1);
            s[nt][3] = __expf(s[nt][3] - mn1);
            ps0 += s[nt][0] + s[nt][1];
            ps1 += s[nt][2] + s[nt][3];
        }
        ps0 += __shfl_xor_sync(0xffffffff, ps0, 1);
        ps0 += __shfl_xor_sync(0xffffffff, ps0, 2);
        ps1 += __shfl_xor_sync(0xffffffff, ps1, 1);
        ps1 += __shfl_xor_sync(0xffffffff, ps1, 2);
        l0 = l0 * a0 + ps0;
        l1 = l1 * a1 + ps1;
        m0 = mn0; m1 = mn1;

        #pragma unroll
        for (int nt = 0; nt < 16; nt++) {
            acc_o[nt][0] *= a0; acc_o[nt][1] *= a0;
            acc_o[nt][2] *= a1; acc_o[nt][3] *= a1;
        }

        uint32_t pf[4][4];
        #pragma unroll
        for (int kt = 0; kt < 4; kt++) {
            pf[kt][0] = h2bits(s[2 * kt][0],     s[2 * kt][1]);
            pf[kt][1] = h2bits(s[2 * kt][2],     s[2 * kt][3]);
            pf[kt][2] = h2bits(s[2 * kt + 1][0], s[2 * kt + 1][1]);
            pf[kt][3] = h2bits(s[2 * kt + 1][2], s[2 * kt + 1][3]);
        }

        {
            int vR = lane & 15;
            uint32_t vC = (uint32_t)((lane >> 4) & 1) * 16;
            #pragma unroll
            for (int kt = 0; kt < 4; kt++) {
                int r = kt * 16 + vR;
                uint32_t rsw = (uint32_t)((r & 7) << 4);
                uint32_t rowb = (uint32_t)(r * 256);
                #pragma unroll
                for (int nn = 0; nn < 8; nn++) {
                    uint32_t byte = (rowb + (uint32_t)(nn * 32) + vC) ^ rsw;
                    uint32_t v0, v1, v2, v3;
                    ldsm4t(v0, v1, v2, v3, SVb[buf] + byte);
                    uint32_t bb0[2] = { v0, v1 }, bb1[2] = { v2, v3 };
                    mma_f16(acc_o[2 * nn],     pf[kt], bb0);
                    mma_f16(acc_o[2 * nn + 1], pf[kt], bb1);
                }
            }
        }
        __syncthreads();
        buf ^= 1;
    }

    float inv0 = 1.f / l0, inv1 = 1.f / l1;
    int gq0 = q0 + warp * 16 + g, gq1 = gq0 + 8;
    #pragma unroll
    for (int nt = 0; nt < 16; nt++) {
        int col = h * DH + nt * 8 + 2 * tg;
        if (gq0 < LQ) {
            __half2 hv = __floats2half2_rn(acc_o[nt][0] * inv0, acc_o[nt][1] * inv0);
            *(__half2*)&h_at[((size_t)b * LQ + gq0) * DM + col] = hv;
        }
        if (gq1 < LQ) {
            __half2 hv = __floats2half2_rn(acc_o[nt][2] * inv1, acc_o[nt][3] * inv1);
            *(__half2*)&h_at[((size_t)b * LQ + gq1) * DM + col] = hv;
        }
    }
}

// ---------------- launcher ----------------
extern "C" void kernel_launch(void* const* d_in, const int* in_sizes, int n_in,
                              void* d_out, int out_size)
{
    const float* tgt = (const float*)d_in[0];
    const float* src = (const float*)d_in[1];
    const float* val = (const float*)d_in[2];
    const float* Wq  = (const float*)d_in[3];
    const float* bq  = (const float*)d_in[4];
    const float* Wk  = (const float*)d_in[5];
    const float* bk  = (const float*)d_in[6];
    const float* Wv  = (const float*)d_in[7];
    const float* bv  = (const float*)d_in[8];
    const float* Wo  = (const float*)d_in[9];
    const float* bo  = (const float*)d_in[10];
    const float* cls = (const float*)d_in[11];

    __half *p_tgt, *p_src, *p_val, *p_wqt, *p_wkt, *p_wvt, *p_wot;
    cudaGetSymbolAddress((void**)&p_tgt, h_tgt);
    cudaGetSymbolAddress((void**)&p_src, h_src);
    cudaGetSymbolAddress((void**)&p_val, h_val);
    cudaGetSymbolAddress((void**)&p_wqt, h_wqt);
    cudaGetSymbolAddress((void**)&p_wkt, h_wkt);
    cudaGetSymbolAddress((void**)&p_wvt, h_wvt);
    cudaGetSymbolAddress((void**)&p_wot, h_wot);

    cudaFuncSetAttribute(qkv_gemm_kernel, cudaFuncAttributeMaxDynamicSharedMemorySize, HGEMM_SMEM);
    cudaFuncSetAttribute(oproj_kernel,    cudaFuncAttributeMaxDynamicSharedMemorySize, HGEMM_SMEM);
    cudaFuncSetAttribute(fattn_kernel,    cudaFuncAttributeMaxDynamicSharedMemorySize, ATTN_SMEM);

    dim3 tb(32, 8);
    transpose_h_kernel<<<dim3(DM / 32,   DM / 32),   tb>>>(Wq, p_wqt, DM,   DM);
    transpose_h_kernel<<<dim3(DM / 32,   DLLM / 32), tb>>>(Wk, p_wkt, DLLM, DM);
    transpose_h_kernel<<<dim3(DM / 32,   DLLM / 32), tb>>>(Wv, p_wvt, DLLM, DM);
    transpose_h_kernel<<<dim3(DLLM / 32, DM / 32),   tb>>>(Wo, p_wot, DM,   DLLM);

    {
        size_t total = (size_t)MQ * (DM / 4);
        build_tgt_h_kernel<<<(int)((total + 255) / 256), 256>>>(tgt, cls, p_tgt);
        size_t n4 = (size_t)SK * DLLM / 4;
        f2h_kernel<<<(int)((n4 + 255) / 256), 256>>>(src, p_src, n4);
        f2h_kernel<<<(int)((n4 + 255) / 256), 256>>>(val, p_val, n4);
    }

    // fused Q/K/V projections, longest tiles first
    qkv_gemm_kernel<<<QKV_BLOCKS, 256, HGEMM_SMEM>>>(bq, bk, bv);
    // attention (half in, half out)
    fattn_kernel<<<dim3((LQ + 63) / 64, NH, B_), 128, ATTN_SMEM>>>();
    // out = attn @ Wo + bo         [16416,4096]  (float out)
    oproj_kernel<<<dim3(DLLM / 128, (MQ + 127) / 128), 256, HGEMM_SMEM>>>(bo, (float*)d_out);
}